// round 2
// baseline (speedup 1.0000x reference)
#include <cuda_runtime.h>
#include <cstdint>

// EdgeModel: out[E,32] = relu([src|dst|ea|u[batch]] @ W1^T + b1) @ W2^T + b2
// Strategy: fold u@W1_u^T + b1 into a per-graph table (4096x64), then a fully
// fused per-edge kernel using packed fp32x2 FFMA (sm_103a) with k-major packed
// weights in shared memory. batch dtype (int32 vs int64) is detected from the
// data: batch is sorted, so the int32 view's last element is ~4095 for int32
// storage and 0 (a high word) for int64 storage.

#define HID 64
#define GBMAX 4096

typedef unsigned long long ull;

__device__ __align__(16) float g_uproj[GBMAX * HID];

__device__ __forceinline__ ull pk(float lo, float hi) {
    ull r; asm("mov.b64 %0, {%1, %2};" : "=l"(r) : "f"(lo), "f"(hi)); return r;
}
__device__ __forceinline__ void upk(ull v, float& lo, float& hi) {
    asm("mov.b64 {%0, %1}, %2;" : "=f"(lo), "=f"(hi) : "l"(v));
}
__device__ __forceinline__ ull ffma2(ull a, ull b, ull c) {
    ull d; asm("fma.rn.f32x2 %0, %1, %2, %3;" : "=l"(d) : "l"(a), "l"(b), "l"(c)); return d;
}

// uproj[b][j] = b1[j] + sum_t u[b][t] * W1[j][96+t]
__global__ void uproj_kernel(const float* __restrict__ u,
                             const float* __restrict__ W1,
                             const float* __restrict__ b1, int nB) {
    int idx = blockIdx.x * blockDim.x + threadIdx.x;
    if (idx >= nB * HID) return;
    int b = idx >> 6;
    int j = idx & 63;
    float acc = b1[j];
    const float* ur = u + b * 16;
    const float* wr = W1 + j * 112 + 96;
#pragma unroll
    for (int t = 0; t < 16; t++) acc = fmaf(ur[t], wr[t], acc);
    g_uproj[idx] = acc;
}

__global__ __launch_bounds__(128) void edge_mlp(
    const float* __restrict__ src, const float* __restrict__ dst,
    const float* __restrict__ ea, const int* __restrict__ batch32,
    const float* __restrict__ W1, const float* __restrict__ W2,
    const float* __restrict__ b2, float* __restrict__ out, int E) {
    // k-major, pair-packed weights: w1s[k][j2] = {W1[2*j2][k], W1[2*j2+1][k]}
    __shared__ ull w1s[96][32];  // 24 KB
    __shared__ ull w2s[64][16];  // 8 KB
    __shared__ ull b2s[16];

    int tid = threadIdx.x;
    for (int i = tid; i < 96 * 32; i += 128) {
        int k = i >> 5, j2 = i & 31;
        w1s[k][j2] = pk(W1[(2 * j2) * 112 + k], W1[(2 * j2 + 1) * 112 + k]);
    }
    for (int i = tid; i < 64 * 16; i += 128) {
        int k = i >> 4, j2 = i & 15;
        w2s[k][j2] = pk(W2[(2 * j2) * 64 + k], W2[(2 * j2 + 1) * 64 + k]);
    }
    if (tid < 16) b2s[tid] = pk(b2[2 * tid], b2[2 * tid + 1]);
    __syncthreads();

    size_t e = (size_t)blockIdx.x * 128 + tid;
    if (e >= (size_t)E) return;

    // ---- batch dtype detection (sorted data; broadcast L2 hits) ----
    // int64 storage: int32 view at odd E-1 is a zero high word, E-2 is ~B/2.
    // int32 storage: E-1 holds the sorted max (~4095), nonzero.
    int tail = batch32[E - 1];
    int tail2 = batch32[E - 2];
    bool is64 = (tail == 0) && (tail2 != 0);
    int gidx = is64 ? batch32[2 * e] : batch32[e];
    gidx = min(max(gidx, 0), GBMAX - 1);

    // h init = uproj[batch[e]]  (b1 + u-contribution pre-folded)
    ull h[32];
    {
        const ulonglong2* up =
            (const ulonglong2*)(g_uproj + (size_t)gidx * HID);
#pragma unroll
        for (int j = 0; j < 16; j++) {
            ulonglong2 v = up[j];
            h[2 * j] = v.x;
            h[2 * j + 1] = v.y;
        }
    }

    // Layer 1: accumulate src (k 0..31), dst (k 32..63), ea (k 64..95)
    const float4* r0 = (const float4*)(src + e * 32);
    const float4* r1 = (const float4*)(dst + e * 32);
    const float4* r2 = (const float4*)(ea + e * 32);

#define ACC4(XV, KBASE)                                              \
    {                                                                \
        const ull* w = &w1s[(KBASE)][0];                             \
        ull xx;                                                      \
        xx = pk((XV).x, (XV).x);                                     \
        _Pragma("unroll") for (int j = 0; j < 32; j++)               \
            h[j] = ffma2(xx, w[j], h[j]);                            \
        xx = pk((XV).y, (XV).y);                                     \
        _Pragma("unroll") for (int j = 0; j < 32; j++)               \
            h[j] = ffma2(xx, w[32 + j], h[j]);                       \
        xx = pk((XV).z, (XV).z);                                     \
        _Pragma("unroll") for (int j = 0; j < 32; j++)               \
            h[j] = ffma2(xx, w[64 + j], h[j]);                       \
        xx = pk((XV).w, (XV).w);                                     \
        _Pragma("unroll") for (int j = 0; j < 32; j++)               \
            h[j] = ffma2(xx, w[96 + j], h[j]);                       \
    }

#pragma unroll 2
    for (int q = 0; q < 8; q++) {
        float4 xv = r0[q];
        ACC4(xv, q * 4);
    }
#pragma unroll 2
    for (int q = 0; q < 8; q++) {
        float4 xv = r1[q];
        ACC4(xv, 32 + q * 4);
    }
#pragma unroll 2
    for (int q = 0; q < 8; q++) {
        float4 xv = r2[q];
        ACC4(xv, 64 + q * 4);
    }
#undef ACC4

    // ReLU + unpack
    float hs[64];
#pragma unroll
    for (int j = 0; j < 32; j++) {
        float lo, hi;
        upk(h[j], lo, hi);
        hs[2 * j] = fmaxf(lo, 0.0f);
        hs[2 * j + 1] = fmaxf(hi, 0.0f);
    }

    // Layer 2: out = hs @ W2^T + b2, packed pairs
    ull o[16];
#pragma unroll
    for (int j = 0; j < 16; j++) o[j] = b2s[j];
#pragma unroll 4
    for (int k = 0; k < 64; k++) {
        ull xx = pk(hs[k], hs[k]);
#pragma unroll
        for (int j = 0; j < 16; j++) o[j] = ffma2(xx, w2s[k][j], o[j]);
    }

    ulonglong2* orow = (ulonglong2*)(out + e * 32);
#pragma unroll
    for (int j = 0; j < 8; j++) {
        ulonglong2 v;
        v.x = o[2 * j];
        v.y = o[2 * j + 1];
        orow[j] = v;
    }
}

extern "C" void kernel_launch(void* const* d_in, const int* in_sizes, int n_in,
                              void* d_out, int out_size) {
    const float* src = (const float*)d_in[0];
    const float* dst = (const float*)d_in[1];
    const float* ea = (const float*)d_in[2];
    const float* u = (const float*)d_in[3];
    const int* batch = (const int*)d_in[4];
    const float* W1 = (const float*)d_in[5];
    const float* b1 = (const float*)d_in[6];
    const float* W2 = (const float*)d_in[7];
    const float* b2 = (const float*)d_in[8];
    float* out = (float*)d_out;

    int E = in_sizes[0] / 32;
    int nB = in_sizes[3] / 16;
    if (nB > GBMAX) nB = GBMAX;

    int tot = nB * HID;
    uproj_kernel<<<(tot + 255) / 256, 256>>>(u, W1, b1, nB);
    edge_mlp<<<(E + 127) / 128, 128>>>(src, dst, ea, batch, W1, W2, b2, out, E);
}

// round 3
// speedup vs baseline: 1.1521x; 1.1521x over previous
#include <cuda_runtime.h>
#include <cstdint>

// EdgeModel: out[E,32] = relu([src|dst|ea|u[batch]] @ W1^T + b1) @ W2^T + b2
// Register-tiled fused MLP: thread tile = 8 edges x 8 hidden, packed fp32x2
// FFMA. u@W1_u^T + b1 folded into per-graph table g_uproj.

#define HID 64
#define GBMAX 4096

typedef unsigned long long ull;

__device__ __align__(16) float g_uproj[GBMAX * HID];

__device__ __forceinline__ ull pk(float lo, float hi) {
    ull r; asm("mov.b64 %0, {%1, %2};" : "=l"(r) : "f"(lo), "f"(hi)); return r;
}
__device__ __forceinline__ void upk(ull v, float& lo, float& hi) {
    asm("mov.b64 {%0, %1}, %2;" : "=f"(lo), "=f"(hi) : "l"(v));
}
__device__ __forceinline__ ull ffma2(ull a, ull b, ull c) {
    ull d; asm("fma.rn.f32x2 %0, %1, %2, %3;" : "=l"(d) : "l"(a), "l"(b), "l"(c)); return d;
}

// uproj[b][j] = b1[j] + sum_t u[b][t] * W1[j][96+t]
__global__ void uproj_kernel(const float* __restrict__ u,
                             const float* __restrict__ W1,
                             const float* __restrict__ b1, int nB) {
    int idx = blockIdx.x * blockDim.x + threadIdx.x;
    if (idx >= nB * HID) return;
    int b = idx >> 6;
    int j = idx & 63;
    float acc = b1[j];
    const float* ur = u + b * 16;
    const float* wr = W1 + j * 112 + 96;
#pragma unroll
    for (int t = 0; t < 16; t++) acc = fmaf(ur[t], wr[t], acc);
    g_uproj[idx] = acc;
}

// Dynamic smem layout (bytes):
//   w1s: ull[96][32]           @ 0       (24576)
//   w2s: ull[64][16]           @ 24576   ( 8192)
//   b2s: ull[16]               @ 32768   (  128)
//   xbuf: 32 KB float buffer   @ 32896
//         layer1: xT[32][132]  (k-major x chunk)
//         layer2: hE[128][64]  (xor-swizzled hidden, reuses same space)
#define SM_W1 0
#define SM_W2 24576
#define SM_B2 32768
#define SM_X  32896
#define SM_TOT (32896 + 32768)

__global__ __launch_bounds__(128) void edge_mlp(
    const float* __restrict__ src, const float* __restrict__ dst,
    const float* __restrict__ ea, const int* __restrict__ batch32,
    const float* __restrict__ W1, const float* __restrict__ W2,
    const float* __restrict__ b2, float* __restrict__ out, int E) {
    extern __shared__ char smem[];
    ull (*w1s)[32] = (ull(*)[32])(smem + SM_W1);
    ull (*w2s)[16] = (ull(*)[16])(smem + SM_W2);
    ull* b2s = (ull*)(smem + SM_B2);
    float* xT = (float*)(smem + SM_X);   // [k][132]
    float* hE = (float*)(smem + SM_X);   // [e][64], col-swizzled

    int tid = threadIdx.x;
    int g = tid & 7;        // hidden group: outputs 8g..8g+7 (4 packed)
    int eg = tid >> 3;      // edge group: local edges 8*eg..8*eg+7
    int e0 = eg * 8;
    int m = e0 & 24;        // xor-swizzle key for hE columns

    // ---- stage weights ----
    for (int i = tid; i < 96 * 32; i += 128) {
        int k = i >> 5, j2 = i & 31;
        w1s[k][j2] = pk(W1[(2 * j2) * 112 + k], W1[(2 * j2 + 1) * 112 + k]);
    }
    for (int i = tid; i < 64 * 16; i += 128) {
        int k = i >> 4, j2 = i & 15;
        w2s[k][j2] = pk(W2[(2 * j2) * 64 + k], W2[(2 * j2 + 1) * 64 + k]);
    }
    if (tid < 16) b2s[tid] = pk(b2[2 * tid], b2[2 * tid + 1]);

    long long eB = (long long)blockIdx.x * 128;

    // ---- batch dtype detection (sorted data) ----
    int tail = batch32[E - 1];
    int tail2 = batch32[E - 2];
    bool is64 = (tail == 0) && (tail2 != 0);

    // ---- acc init = uproj[batch[e]][8g..8g+7] (b1 + u pre-folded) ----
    ull acc[8][4];
#pragma unroll
    for (int i = 0; i < 8; i++) {
        long long e = eB + e0 + i;
        if (e >= E) e = E - 1;
        int gidx = is64 ? batch32[2 * e] : batch32[e];
        gidx = min(max(gidx, 0), GBMAX - 1);
        const ulonglong2* up =
            (const ulonglong2*)(g_uproj + (size_t)gidx * HID + g * 8);
        ulonglong2 v0 = up[0], v1 = up[1];
        acc[i][0] = v0.x; acc[i][1] = v0.y;
        acc[i][2] = v1.x; acc[i][3] = v1.y;
    }

    // ---- layer 1: three K=32 chunks (src, dst, ea) ----
    long long eld = eB + tid;
    if (eld >= E) eld = E - 1;
#pragma unroll 1
    for (int c = 0; c < 3; c++) {
        const float* A = (c == 0) ? src : (c == 1) ? dst : ea;
        const float4* row = (const float4*)(A + eld * 32);
        __syncthreads();  // previous chunk reads done before overwrite
#pragma unroll
        for (int q = 0; q < 8; q++) {
            float4 v = row[q];
            xT[(4 * q + 0) * 132 + tid] = v.x;
            xT[(4 * q + 1) * 132 + tid] = v.y;
            xT[(4 * q + 2) * 132 + tid] = v.z;
            xT[(4 * q + 3) * 132 + tid] = v.w;
        }
        __syncthreads();
#pragma unroll 2
        for (int k = 0; k < 32; k++) {
            float4 xa = *(const float4*)&xT[k * 132 + e0];
            float4 xb = *(const float4*)&xT[k * 132 + e0 + 4];
            ulonglong2 wv0 = *(const ulonglong2*)&w1s[c * 32 + k][4 * g];
            ulonglong2 wv1 = *(const ulonglong2*)&w1s[c * 32 + k][4 * g + 2];
            float xs[8] = {xa.x, xa.y, xa.z, xa.w, xb.x, xb.y, xb.z, xb.w};
#pragma unroll
            for (int i = 0; i < 8; i++) {
                ull xx = pk(xs[i], xs[i]);
                acc[i][0] = ffma2(xx, wv0.x, acc[i][0]);
                acc[i][1] = ffma2(xx, wv0.y, acc[i][1]);
                acc[i][2] = ffma2(xx, wv1.x, acc[i][2]);
                acc[i][3] = ffma2(xx, wv1.y, acc[i][3]);
            }
        }
    }

    // ---- relu, write h to swizzled smem (hE aliases xT) ----
    __syncthreads();
    {
        float* dstp = hE;  // [e][64] physical col = logical col ^ m
#pragma unroll
        for (int i = 0; i < 8; i++) {
            float h[8];
#pragma unroll
            for (int j = 0; j < 4; j++) {
                float lo, hi;
                upk(acc[i][j], lo, hi);
                h[2 * j] = fmaxf(lo, 0.0f);
                h[2 * j + 1] = fmaxf(hi, 0.0f);
            }
            float4* p = (float4*)&dstp[(e0 + i) * 64 + ((8 * g) ^ m)];
            p[0] = make_float4(h[0], h[1], h[2], h[3]);
            p[1] = make_float4(h[4], h[5], h[6], h[7]);
        }
    }
    __syncthreads();

    // ---- layer 2: out = relu(h) @ W2^T + b2 ----
    ull o[8][2];
    {
        ull bb0 = b2s[2 * g], bb1 = b2s[2 * g + 1];
#pragma unroll
        for (int i = 0; i < 8; i++) { o[i][0] = bb0; o[i][1] = bb1; }
    }
#pragma unroll 4
    for (int k = 0; k < 64; k++) {
        ulonglong2 wv = *(const ulonglong2*)&w2s[k][2 * g];
        int kc = k ^ m;
#pragma unroll
        for (int i = 0; i < 8; i++) {
            float x = hE[(e0 + i) * 64 + kc];
            ull xx = pk(x, x);
            o[i][0] = ffma2(xx, wv.x, o[i][0]);
            o[i][1] = ffma2(xx, wv.y, o[i][1]);
        }
    }

    // ---- store: thread writes outputs 4g..4g+3 for its 8 edges ----
#pragma unroll
    for (int i = 0; i < 8; i++) {
        long long e = eB + e0 + i;
        if (e < E) {
            ulonglong2 v; v.x = o[i][0]; v.y = o[i][1];
            *(ulonglong2*)(out + e * 32 + 4 * g) = v;
        }
    }
}

extern "C" void kernel_launch(void* const* d_in, const int* in_sizes, int n_in,
                              void* d_out, int out_size) {
    const float* src = (const float*)d_in[0];
    const float* dst = (const float*)d_in[1];
    const float* ea = (const float*)d_in[2];
    const float* u = (const float*)d_in[3];
    const int* batch = (const int*)d_in[4];
    const float* W1 = (const float*)d_in[5];
    const float* b1 = (const float*)d_in[6];
    const float* W2 = (const float*)d_in[7];
    const float* b2 = (const float*)d_in[8];
    float* out = (float*)d_out;

    int E = in_sizes[0] / 32;
    int nB = in_sizes[3] / 16;
    if (nB > GBMAX) nB = GBMAX;

    static int smem_set = 0;
    if (!smem_set) {
        cudaFuncSetAttribute(edge_mlp, cudaFuncAttributeMaxDynamicSharedMemorySize,
                             SM_TOT);
        smem_set = 1;
    }

    int tot = nB * HID;
    uproj_kernel<<<(tot + 255) / 256, 256>>>(u, W1, b1, nB);
    int nblk = (E + 127) / 128;
    edge_mlp<<<nblk, 128, SM_TOT>>>(src, dst, ea, batch, W1, W2, b2, out, E);
}

// round 5
// speedup vs baseline: 2.4947x; 2.1653x over previous
#include <cuda_runtime.h>
#include <cuda_bf16.h>

// EdgeModel via mma.sync.m16n8k16 bf16 3-split GEMMs (fallback HMMA path;
// tcgen05 PTX is rejected by the harness's compute_103 virtual arch).
//   h = relu([src|dst|ea|u[batch]] @ W1^T + b1); out = h @ W2^T + b2
// x and W split into bf16 hi+lo; D += Ahi*Bhi + Ahi*Blo + Alo*Bhi (fp32 acc).

typedef unsigned int u32;

#define GBMAX 4096
#define TPC 5  // 128-edge tiles per block

// ---- smem layout (bytes). W staging aliases the A region (freed after
// weight fragments are ldmatrix'ed into registers). ----
#define SMA_HI 0              // A1 hi: 128 rows x 240B
#define SMA_LO 30720          // A1 lo
#define SMH_HI 61440          // h hi: 128 rows x 144B
#define SMH_LO 79872          // h lo
#define SM_TOTAL 98304
#define SW1_HI 0              // W1 hi: 64 rows x 272B (k-pad 136 bf16)
#define SW1_LO 17408
#define SW2_HI 34816          // W2 hi: 32 rows x 144B (k-pad 72 bf16)
#define SW2_LO 39424
#define WT_BYTES 44032

#define A_STRIDE 240
#define H_STRIDE 144
#define W1_STRIDE 272
#define W2_STRIDE 144

__device__ __align__(16) unsigned char g_wt[WT_BYTES];

// ---- helpers ----
__device__ __forceinline__ u32 smem_u32(const void* p) {
    u32 a;
    asm("{ .reg .u64 t; cvta.to.shared.u64 t, %1; cvt.u32.u64 %0, t; }"
        : "=r"(a) : "l"(p));
    return a;
}
__device__ __forceinline__ void ldmx4(u32* r, u32 addr) {
    asm volatile("ldmatrix.sync.aligned.m8n8.x4.shared.b16 {%0,%1,%2,%3}, [%4];"
                 : "=r"(r[0]), "=r"(r[1]), "=r"(r[2]), "=r"(r[3]) : "r"(addr));
}
__device__ __forceinline__ void ldmx2(u32* r, u32 addr) {
    asm volatile("ldmatrix.sync.aligned.m8n8.x2.shared.b16 {%0,%1}, [%2];"
                 : "=r"(r[0]), "=r"(r[1]) : "r"(addr));
}
__device__ __forceinline__ void mma_bf16(float& c0, float& c1, float& c2,
                                         float& c3, const u32* a, u32 b0,
                                         u32 b1) {
    asm volatile(
        "mma.sync.aligned.m16n8k16.row.col.f32.bf16.bf16.f32 "
        "{%0,%1,%2,%3}, {%4,%5,%6,%7}, {%8,%9}, {%0,%1,%2,%3};"
        : "+f"(c0), "+f"(c1), "+f"(c2), "+f"(c3)
        : "r"(a[0]), "r"(a[1]), "r"(a[2]), "r"(a[3]), "r"(b0), "r"(b1));
}
__device__ __forceinline__ void split2(float a, float b, u32& hi, u32& lo) {
    __nv_bfloat16 ah = __float2bfloat16(a), bh = __float2bfloat16(b);
    float ar = a - __bfloat162float(ah), br = b - __bfloat162float(bh);
    __nv_bfloat16 al = __float2bfloat16(ar), bl = __float2bfloat16(br);
    hi = (u32)__bfloat16_as_ushort(ah) | ((u32)__bfloat16_as_ushort(bh) << 16);
    lo = (u32)__bfloat16_as_ushort(al) | ((u32)__bfloat16_as_ushort(bl) << 16);
}

// ---- weight prep: split fp32 -> bf16 hi/lo into [n][k]-row-major blob ----
__global__ void prep_kernel(const float* __restrict__ W1,
                            const float* __restrict__ W2) {
    int i = blockIdx.x * blockDim.x + threadIdx.x;
    if (i < 64 * 136) {  // W1: n 0..63, k pad to 136
        int n = i / 136, k = i % 136;
        float v = (k < 112) ? W1[n * 112 + k] : 0.0f;
        __nv_bfloat16 h = __float2bfloat16(v);
        float r = v - __bfloat162float(h);
        __nv_bfloat16 l = __float2bfloat16(r);
        int off = n * W1_STRIDE + k * 2;
        *(unsigned short*)(g_wt + SW1_HI + off) = __bfloat16_as_ushort(h);
        *(unsigned short*)(g_wt + SW1_LO + off) = __bfloat16_as_ushort(l);
    } else if (i < 64 * 136 + 32 * 72) {  // W2: n 0..31, k pad to 72
        int j = i - 64 * 136;
        int n = j / 72, k = j % 72;
        float v = (k < 64) ? W2[n * 64 + k] : 0.0f;
        __nv_bfloat16 h = __float2bfloat16(v);
        float r = v - __bfloat162float(h);
        __nv_bfloat16 l = __float2bfloat16(r);
        int off = n * W2_STRIDE + k * 2;
        *(unsigned short*)(g_wt + SW2_HI + off) = __bfloat16_as_ushort(h);
        *(unsigned short*)(g_wt + SW2_LO + off) = __bfloat16_as_ushort(l);
    }
}

// ---- main kernel: 256 threads, 8 warps; warp w owns L1 N-tile w (n=8w..8w+7)
// and L2 N-tile (w&3) over subtile half (w>>2). ----
__global__ __launch_bounds__(256, 2) void edge_mma(
    const float* __restrict__ src, const float* __restrict__ dst,
    const float* __restrict__ ea, const float* __restrict__ u,
    const int* __restrict__ batch32, const float* __restrict__ b1,
    const float* __restrict__ b2, float* __restrict__ out, int E, int nB) {
    extern __shared__ char sm[];
    u32 sb = smem_u32(sm);
    int tid = threadIdx.x;
    int l = tid & 31, w = tid >> 5;
    int tg = l & 3, g = l >> 2;

    // stage prepped weights (aliases A region)
    {
        const uint4* gw = (const uint4*)g_wt;
        uint4* sw = (uint4*)sm;
        for (int i = tid; i < WT_BYTES / 16; i += 256) sw[i] = gw[i];
    }
    __syncthreads();

    // ldmatrix B fragments into registers (x2: lanes 0-15 supply addrs)
    int lw = l & 15;
    int colsel = ((lw >> 3) & 1) * 16;
    u32 b1f[7][2][2], b2f[4][2][2];
    {
        u32 rbase = sb + (u32)((w * 8 + (lw & 7)) * W1_STRIDE) + colsel;
#pragma unroll
        for (int c = 0; c < 7; c++) {
            ldmx2(b1f[c][0], rbase + SW1_HI + c * 32);
            ldmx2(b1f[c][1], rbase + SW1_LO + c * 32);
        }
        u32 rb2 = sb + (u32)(((w & 3) * 8 + (lw & 7)) * W2_STRIDE) + colsel;
#pragma unroll
        for (int c = 0; c < 4; c++) {
            ldmx2(b2f[c][0], rb2 + SW2_HI + c * 32);
            ldmx2(b2f[c][1], rb2 + SW2_LO + c * 32);
        }
    }
    float bb1a = b1[w * 8 + 2 * tg], bb1b = b1[w * 8 + 2 * tg + 1];
    float bb2a = b2[(w & 3) * 8 + 2 * tg], bb2b = b2[(w & 3) * 8 + 2 * tg + 1];

    // batch dtype detection (sorted data; int64 high word at odd tail == 0)
    int tail = batch32[E - 1];
    int tail2 = batch32[E - 2];
    bool is64 = (tail == 0) && (tail2 != 0);

    __syncthreads();  // fragments loaded before A staging overwrites W region

    for (int t = 0; t < TPC; t++) {
        long long eB = ((long long)blockIdx.x * TPC + t) * 128;
        if (eB >= (long long)E) break;

        // ---- stage A: 2 threads per edge, bf16 hi/lo with u[batch] fold ----
        {
            int el = tid >> 1, half = tid & 1;
            long long e = eB + el;
            if (e >= E) e = E - 1;
            int gidx = is64 ? batch32[2 * e] : batch32[e];
            gidx = min(max(gidx, 0), nB - 1);
            const float4* ps = (const float4*)(src + e * 32);
            const float4* pd = (const float4*)(dst + e * 32);
            const float4* pe = (const float4*)(ea + e * 32);
            const float4* pu = (const float4*)(u + (size_t)gidx * 16);
            u32 rowoff = (u32)(el * A_STRIDE + 112 * half);
#pragma unroll
            for (int j = 0; j < 14; j++) {
                float4 v;
                if (half == 0) {
                    v = (j < 8) ? ps[j] : pd[j - 8];
                } else {
                    v = (j < 2) ? pd[j + 6] : (j < 10) ? pe[j - 2] : pu[j - 10];
                }
                u32 h0, l0, h1, l1;
                split2(v.x, v.y, h0, l0);
                split2(v.z, v.w, h1, l1);
                *(uint2*)(sm + SMA_HI + rowoff + 8 * j) = make_uint2(h0, h1);
                *(uint2*)(sm + SMA_LO + rowoff + 8 * j) = make_uint2(l0, l1);
            }
        }
        __syncthreads();

        // ---- layer 1: warp w computes cols 8w..8w+7 for all 8 subtiles ----
        u32 lrow = (u32)(((l & 7) + ((l >> 3) & 1) * 8));
        u32 ksel = ((l >> 4) & 1) * 16;
#pragma unroll 1
        for (int s = 0; s < 8; s++) {
            float c0 = 0.f, c1 = 0.f, c2 = 0.f, c3 = 0.f;
            u32 abase = sb + (u32)((s * 16 + lrow) * A_STRIDE) + ksel;
#pragma unroll
            for (int c = 0; c < 7; c++) {
                u32 ah[4], al[4];
                ldmx4(ah, abase + SMA_HI + c * 32);
                ldmx4(al, abase + SMA_LO + c * 32);
                mma_bf16(c0, c1, c2, c3, ah, b1f[c][0][0], b1f[c][0][1]);
                mma_bf16(c0, c1, c2, c3, ah, b1f[c][1][0], b1f[c][1][1]);
                mma_bf16(c0, c1, c2, c3, al, b1f[c][0][0], b1f[c][0][1]);
            }
            float h0 = fmaxf(c0 + bb1a, 0.f), h1 = fmaxf(c1 + bb1b, 0.f);
            float h2 = fmaxf(c2 + bb1a, 0.f), h3 = fmaxf(c3 + bb1b, 0.f);
            u32 hi01, lo01, hi23, lo23;
            split2(h0, h1, hi01, lo01);
            split2(h2, h3, hi23, lo23);
            int r0 = s * 16 + g;
            int colb = (w * 8 + 2 * tg) * 2;
            *(u32*)(sm + SMH_HI + r0 * H_STRIDE + colb) = hi01;
            *(u32*)(sm + SMH_LO + r0 * H_STRIDE + colb) = lo01;
            *(u32*)(sm + SMH_HI + (r0 + 8) * H_STRIDE + colb) = hi23;
            *(u32*)(sm + SMH_LO + (r0 + 8) * H_STRIDE + colb) = lo23;
        }
        __syncthreads();

        // ---- layer 2: warp w -> N-tile (w&3), subtiles (w>>2)*4 .. +3 ----
        int s0 = (w >> 2) * 4;
#pragma unroll
        for (int si = 0; si < 4; si++) {
            int s = s0 + si;
            float c0 = 0.f, c1 = 0.f, c2 = 0.f, c3 = 0.f;
            u32 hbase = sb + (u32)((s * 16 + lrow) * H_STRIDE) + ksel;
#pragma unroll
            for (int c = 0; c < 4; c++) {
                u32 ah[4], al[4];
                ldmx4(ah, hbase + SMH_HI + c * 32);
                ldmx4(al, hbase + SMH_LO + c * 32);
                mma_bf16(c0, c1, c2, c3, ah, b2f[c][0][0], b2f[c][0][1]);
                mma_bf16(c0, c1, c2, c3, ah, b2f[c][1][0], b2f[c][1][1]);
                mma_bf16(c0, c1, c2, c3, al, b2f[c][0][0], b2f[c][0][1]);
            }
            long long e0 = eB + s * 16 + g;
            int col = (w & 3) * 8 + 2 * tg;
            if (e0 < E)
                *(float2*)(out + e0 * 32 + col) =
                    make_float2(c0 + bb2a, c1 + bb2b);
            if (e0 + 8 < E)
                *(float2*)(out + (e0 + 8) * 32 + col) =
                    make_float2(c2 + bb2a, c3 + bb2b);
        }
        __syncthreads();  // h/A reads done before next tile restages
    }
}

extern "C" void kernel_launch(void* const* d_in, const int* in_sizes, int n_in,
                              void* d_out, int out_size) {
    const float* src = (const float*)d_in[0];
    const float* dst = (const float*)d_in[1];
    const float* ea = (const float*)d_in[2];
    const float* u = (const float*)d_in[3];
    const int* batch = (const int*)d_in[4];
    const float* W1 = (const float*)d_in[5];
    const float* b1 = (const float*)d_in[6];
    const float* W2 = (const float*)d_in[7];
    const float* b2 = (const float*)d_in[8];
    float* out = (float*)d_out;

    int E = in_sizes[0] / 32;
    int nB = in_sizes[3] / 16;
    if (nB > GBMAX) nB = GBMAX;

    static int init_done = 0;
    if (!init_done) {
        cudaFuncSetAttribute(edge_mma,
                             cudaFuncAttributeMaxDynamicSharedMemorySize,
                             SM_TOTAL);
        init_done = 1;
    }

    prep_kernel<<<43, 256>>>(W1, W2);
    long long tiles = ((long long)E + 127) / 128;
    int grid = (int)((tiles + TPC - 1) / TPC);
    edge_mma<<<grid, 256, SM_TOTAL>>>(src, dst, ea, u, batch, b1, b2, out, E,
                                      nB);
}

// round 6
// speedup vs baseline: 3.0808x; 1.2349x over previous
#include <cuda_runtime.h>
#include <cuda_bf16.h>

// EdgeModel via mma.sync.m16n8k16 bf16 3-split GEMMs.
//   h = relu([src|dst|ea|u[batch]] @ W1^T + b1); out = h @ W2^T + b2
// R6: N=16 per warp in both layers -> A/h ldmatrix redundancy halved
// (L1tex was 86% binding at 8-way A-fragment sharing).

typedef unsigned int u32;

#define GBMAX 4096
#define TPC 5  // 128-edge tiles per block

// ---- smem layout (bytes). W staging aliases the A region. ----
#define SMA_HI 0              // A1 hi: 128 rows x 240B
#define SMA_LO 30720          // A1 lo
#define SMH_HI 61440          // h hi: 128 rows x 144B
#define SMH_LO 79872          // h lo
#define SM_TOTAL 98304
#define SW1_HI 0              // W1 hi: 64 rows x 272B (k-pad 136 bf16)
#define SW1_LO 17408
#define SW2_HI 34816          // W2 hi: 32 rows x 144B (k-pad 72 bf16)
#define SW2_LO 39424
#define WT_BYTES 44032

#define A_STRIDE 240
#define H_STRIDE 144
#define W1_STRIDE 272
#define W2_STRIDE 144

__device__ __align__(16) unsigned char g_wt[WT_BYTES];

// ---- helpers ----
__device__ __forceinline__ u32 smem_u32(const void* p) {
    u32 a;
    asm("{ .reg .u64 t; cvta.to.shared.u64 t, %1; cvt.u32.u64 %0, t; }"
        : "=r"(a) : "l"(p));
    return a;
}
__device__ __forceinline__ void ldmx4(u32* r, u32 addr) {
    asm volatile("ldmatrix.sync.aligned.m8n8.x4.shared.b16 {%0,%1,%2,%3}, [%4];"
                 : "=r"(r[0]), "=r"(r[1]), "=r"(r[2]), "=r"(r[3]) : "r"(addr));
}
__device__ __forceinline__ void ldmx2(u32* r, u32 addr) {
    asm volatile("ldmatrix.sync.aligned.m8n8.x2.shared.b16 {%0,%1}, [%2];"
                 : "=r"(r[0]), "=r"(r[1]) : "r"(addr));
}
__device__ __forceinline__ void mma_bf16(float* c, const u32* a, u32 b0,
                                         u32 b1) {
    asm volatile(
        "mma.sync.aligned.m16n8k16.row.col.f32.bf16.bf16.f32 "
        "{%0,%1,%2,%3}, {%4,%5,%6,%7}, {%8,%9}, {%0,%1,%2,%3};"
        : "+f"(c[0]), "+f"(c[1]), "+f"(c[2]), "+f"(c[3])
        : "r"(a[0]), "r"(a[1]), "r"(a[2]), "r"(a[3]), "r"(b0), "r"(b1));
}
__device__ __forceinline__ void split2(float a, float b, u32& hi, u32& lo) {
    __nv_bfloat16 ah = __float2bfloat16(a), bh = __float2bfloat16(b);
    float ar = a - __bfloat162float(ah), br = b - __bfloat162float(bh);
    __nv_bfloat16 al = __float2bfloat16(ar), bl = __float2bfloat16(br);
    hi = (u32)__bfloat16_as_ushort(ah) | ((u32)__bfloat16_as_ushort(bh) << 16);
    lo = (u32)__bfloat16_as_ushort(al) | ((u32)__bfloat16_as_ushort(bl) << 16);
}

// ---- weight prep: split fp32 -> bf16 hi/lo into [n][k]-row-major blob ----
__global__ void prep_kernel(const float* __restrict__ W1,
                            const float* __restrict__ W2) {
    int i = blockIdx.x * blockDim.x + threadIdx.x;
    if (i < 64 * 136) {  // W1: n 0..63, k pad to 136
        int n = i / 136, k = i % 136;
        float v = (k < 112) ? W1[n * 112 + k] : 0.0f;
        __nv_bfloat16 h = __float2bfloat16(v);
        float r = v - __bfloat162float(h);
        __nv_bfloat16 l = __float2bfloat16(r);
        int off = n * W1_STRIDE + k * 2;
        *(unsigned short*)(g_wt + SW1_HI + off) = __bfloat16_as_ushort(h);
        *(unsigned short*)(g_wt + SW1_LO + off) = __bfloat16_as_ushort(l);
    } else if (i < 64 * 136 + 32 * 72) {  // W2: n 0..31, k pad to 72
        int j = i - 64 * 136;
        int n = j / 72, k = j % 72;
        float v = (k < 64) ? W2[n * 64 + k] : 0.0f;
        __nv_bfloat16 h = __float2bfloat16(v);
        float r = v - __bfloat162float(h);
        __nv_bfloat16 l = __float2bfloat16(r);
        int off = n * W2_STRIDE + k * 2;
        *(unsigned short*)(g_wt + SW2_HI + off) = __bfloat16_as_ushort(h);
        *(unsigned short*)(g_wt + SW2_LO + off) = __bfloat16_as_ushort(l);
    }
}

// ---- main kernel: 256 threads / 8 warps.
// L1: warp = (s2 = w>>2: 4 subtiles, nh = w&3: N=16 = 2 ntiles)
// L2: warp = (s4 = w>>1: 2 subtiles, nh2 = w&1: N=16 = 2 ntiles) ----
__global__ __launch_bounds__(256, 2) void edge_mma(
    const float* __restrict__ src, const float* __restrict__ dst,
    const float* __restrict__ ea, const float* __restrict__ u,
    const int* __restrict__ batch32, const float* __restrict__ b1,
    const float* __restrict__ b2, float* __restrict__ out, int E, int nB) {
    extern __shared__ char sm[];
    u32 sb = smem_u32(sm);
    int tid = threadIdx.x;
    int l = tid & 31, w = tid >> 5;
    int tg = l & 3, g = l >> 2;
    int nh = w & 3, s2 = w >> 2;    // layer-1 roles
    int nh2 = w & 1, s4 = w >> 1;   // layer-2 roles

    // stage prepped weights (aliases A region)
    {
        const uint4* gw = (const uint4*)g_wt;
        uint4* sw = (uint4*)sm;
        for (int i = tid; i < WT_BYTES / 16; i += 256) sw[i] = gw[i];
    }
    __syncthreads();

    // ldmatrix B fragments into registers
    int lw = l & 15;
    int colsel = ((lw >> 3) & 1) * 16;
    u32 b1f[7][2][2][2];  // [chunk][ntile][split][reg]
    u32 b2f[4][2][2][2];
    {
#pragma unroll
        for (int nt = 0; nt < 2; nt++) {
            u32 rbase =
                sb + (u32)((nh * 16 + nt * 8 + (lw & 7)) * W1_STRIDE) + colsel;
#pragma unroll
            for (int c = 0; c < 7; c++) {
                ldmx2(b1f[c][nt][0], rbase + SW1_HI + c * 32);
                ldmx2(b1f[c][nt][1], rbase + SW1_LO + c * 32);
            }
            u32 rb2 =
                sb + (u32)((nh2 * 16 + nt * 8 + (lw & 7)) * W2_STRIDE) + colsel;
#pragma unroll
            for (int c = 0; c < 4; c++) {
                ldmx2(b2f[c][nt][0], rb2 + SW2_HI + c * 32);
                ldmx2(b2f[c][nt][1], rb2 + SW2_LO + c * 32);
            }
        }
    }
    float bb1[2][2], bb2[2][2];
#pragma unroll
    for (int nt = 0; nt < 2; nt++) {
        bb1[nt][0] = b1[nh * 16 + nt * 8 + 2 * tg];
        bb1[nt][1] = b1[nh * 16 + nt * 8 + 2 * tg + 1];
        bb2[nt][0] = b2[nh2 * 16 + nt * 8 + 2 * tg];
        bb2[nt][1] = b2[nh2 * 16 + nt * 8 + 2 * tg + 1];
    }

    // batch dtype detection (sorted data; int64 high word at odd tail == 0)
    int tail = batch32[E - 1];
    int tail2 = batch32[E - 2];
    bool is64 = (tail == 0) && (tail2 != 0);

    __syncthreads();  // fragments loaded before A staging overwrites W region

    u32 lrow = (u32)(((l & 7) + ((l >> 3) & 1) * 8));
    u32 ksel = ((l >> 4) & 1) * 16;

    for (int t = 0; t < TPC; t++) {
        long long eB = ((long long)blockIdx.x * TPC + t) * 128;
        if (eB >= (long long)E) break;

        // ---- stage A: 2 threads per edge, bf16 hi/lo with u[batch] fold ----
        {
            int el = tid >> 1, half = tid & 1;
            long long e = eB + el;
            if (e >= E) e = E - 1;
            int gidx = is64 ? batch32[2 * e] : batch32[e];
            gidx = min(max(gidx, 0), nB - 1);
            const float4* ps = (const float4*)(src + e * 32);
            const float4* pd = (const float4*)(dst + e * 32);
            const float4* pe = (const float4*)(ea + e * 32);
            const float4* pu = (const float4*)(u + (size_t)gidx * 16);
            u32 rowoff = (u32)(el * A_STRIDE + 112 * half);
#pragma unroll
            for (int j = 0; j < 14; j++) {
                float4 v;
                if (half == 0) {
                    v = (j < 8) ? ps[j] : pd[j - 8];
                } else {
                    v = (j < 2) ? pd[j + 6] : (j < 10) ? pe[j - 2] : pu[j - 10];
                }
                u32 h0, l0, h1, l1;
                split2(v.x, v.y, h0, l0);
                split2(v.z, v.w, h1, l1);
                *(uint2*)(sm + SMA_HI + rowoff + 8 * j) = make_uint2(h0, h1);
                *(uint2*)(sm + SMA_LO + rowoff + 8 * j) = make_uint2(l0, l1);
            }
        }
        __syncthreads();

        // ---- layer 1: warp covers 4 subtiles x N=16 ----
#pragma unroll 1
        for (int si = 0; si < 4; si++) {
            int s = s2 * 4 + si;
            float acc[2][4] = {{0.f, 0.f, 0.f, 0.f}, {0.f, 0.f, 0.f, 0.f}};
            u32 abase = sb + (u32)((s * 16 + lrow) * A_STRIDE) + ksel;
#pragma unroll
            for (int c = 0; c < 7; c++) {
                u32 ah[4], al[4];
                ldmx4(ah, abase + SMA_HI + c * 32);
                ldmx4(al, abase + SMA_LO + c * 32);
#pragma unroll
                for (int nt = 0; nt < 2; nt++) {
                    mma_bf16(acc[nt], ah, b1f[c][nt][0][0], b1f[c][nt][0][1]);
                    mma_bf16(acc[nt], ah, b1f[c][nt][1][0], b1f[c][nt][1][1]);
                    mma_bf16(acc[nt], al, b1f[c][nt][0][0], b1f[c][nt][0][1]);
                }
            }
#pragma unroll
            for (int nt = 0; nt < 2; nt++) {
                float h0 = fmaxf(acc[nt][0] + bb1[nt][0], 0.f);
                float h1 = fmaxf(acc[nt][1] + bb1[nt][1], 0.f);
                float h2 = fmaxf(acc[nt][2] + bb1[nt][0], 0.f);
                float h3 = fmaxf(acc[nt][3] + bb1[nt][1], 0.f);
                u32 hi01, lo01, hi23, lo23;
                split2(h0, h1, hi01, lo01);
                split2(h2, h3, hi23, lo23);
                int r0 = s * 16 + g;
                int colb = (nh * 16 + nt * 8 + 2 * tg) * 2;
                *(u32*)(sm + SMH_HI + r0 * H_STRIDE + colb) = hi01;
                *(u32*)(sm + SMH_LO + r0 * H_STRIDE + colb) = lo01;
                *(u32*)(sm + SMH_HI + (r0 + 8) * H_STRIDE + colb) = hi23;
                *(u32*)(sm + SMH_LO + (r0 + 8) * H_STRIDE + colb) = lo23;
            }
        }
        __syncthreads();

        // ---- layer 2: warp covers 2 subtiles x N=16 ----
#pragma unroll
        for (int si = 0; si < 2; si++) {
            int s = s4 * 2 + si;
            float acc[2][4] = {{0.f, 0.f, 0.f, 0.f}, {0.f, 0.f, 0.f, 0.f}};
            u32 hbase = sb + (u32)((s * 16 + lrow) * H_STRIDE) + ksel;
#pragma unroll
            for (int c = 0; c < 4; c++) {
                u32 ah[4], al[4];
                ldmx4(ah, hbase + SMH_HI + c * 32);
                ldmx4(al, hbase + SMH_LO + c * 32);
#pragma unroll
                for (int nt = 0; nt < 2; nt++) {
                    mma_bf16(acc[nt], ah, b2f[c][nt][0][0], b2f[c][nt][0][1]);
                    mma_bf16(acc[nt], ah, b2f[c][nt][1][0], b2f[c][nt][1][1]);
                    mma_bf16(acc[nt], al, b2f[c][nt][0][0], b2f[c][nt][0][1]);
                }
            }
            long long e0 = eB + s * 16 + g;
#pragma unroll
            for (int nt = 0; nt < 2; nt++) {
                int col = nh2 * 16 + nt * 8 + 2 * tg;
                if (e0 < E)
                    *(float2*)(out + e0 * 32 + col) =
                        make_float2(acc[nt][0] + bb2[nt][0],
                                    acc[nt][1] + bb2[nt][1]);
                if (e0 + 8 < E)
                    *(float2*)(out + (e0 + 8) * 32 + col) =
                        make_float2(acc[nt][2] + bb2[nt][0],
                                    acc[nt][3] + bb2[nt][1]);
            }
        }
        __syncthreads();  // h/A reads done before next tile restages
    }
}

extern "C" void kernel_launch(void* const* d_in, const int* in_sizes, int n_in,
                              void* d_out, int out_size) {
    const float* src = (const float*)d_in[0];
    const float* dst = (const float*)d_in[1];
    const float* ea = (const float*)d_in[2];
    const float* u = (const float*)d_in[3];
    const int* batch = (const int*)d_in[4];
    const float* W1 = (const float*)d_in[5];
    const float* b1 = (const float*)d_in[6];
    const float* W2 = (const float*)d_in[7];
    const float* b2 = (const float*)d_in[8];
    float* out = (float*)d_out;

    int E = in_sizes[0] / 32;
    int nB = in_sizes[3] / 16;
    if (nB > GBMAX) nB = GBMAX;

    static int init_done = 0;
    if (!init_done) {
        cudaFuncSetAttribute(edge_mma,
                             cudaFuncAttributeMaxDynamicSharedMemorySize,
                             SM_TOTAL);
        init_done = 1;
    }

    prep_kernel<<<43, 256>>>(W1, W2);
    long long tiles = ((long long)E + 127) / 128;
    int grid = (int)((tiles + TPC - 1) / TPC);
    edge_mma<<<grid, 256, SM_TOTAL>>>(src, dst, ea, u, batch, b1, b2, out, E,
                                      nB);
}

// round 7
// speedup vs baseline: 4.5107x; 1.4641x over previous
#include <cuda_runtime.h>
#include <cuda_fp16.h>

// EdgeModel via single-precision fp16 mma.sync.m16n8k16 (fp32 accum).
//   h = relu([src|dst|ea|u[batch]] @ W1^T + b1); out = h @ W2^T + b2
// R7: replace bf16 3-split with single fp16 MMA (fp16 rounding 2^-12 ->
// norm rel_err ~5e-4 < 1e-3). Halves staging bytes, 1/3 the MMAs, and
// layer-1 widens to N=32/warp (A-fragment redundancy halved again).

typedef unsigned int u32;

#define GBMAX 4096
#define TPC 5  // 128-edge tiles per block

// ---- smem layout (bytes). W staging aliases the A region. ----
#define SMA 0            // A: 128 rows x 240B (112 fp16 + pad)
#define SMH 30720        // h: 128 rows x 144B (64 fp16 + pad)
#define SM_TOTAL 49152
#define SW1 0            // W1: 64 rows x 272B (k-pad 136 fp16)
#define SW2 17408        // W2: 32 rows x 144B (k-pad 72 fp16)
#define WT_BYTES 22016

#define A_STRIDE 240
#define H_STRIDE 144
#define W1_STRIDE 272
#define W2_STRIDE 144

__device__ __align__(16) unsigned char g_wt[WT_BYTES];

// ---- helpers ----
__device__ __forceinline__ u32 smem_u32(const void* p) {
    u32 a;
    asm("{ .reg .u64 t; cvta.to.shared.u64 t, %1; cvt.u32.u64 %0, t; }"
        : "=r"(a) : "l"(p));
    return a;
}
__device__ __forceinline__ void ldmx4(u32* r, u32 addr) {
    asm volatile("ldmatrix.sync.aligned.m8n8.x4.shared.b16 {%0,%1,%2,%3}, [%4];"
                 : "=r"(r[0]), "=r"(r[1]), "=r"(r[2]), "=r"(r[3]) : "r"(addr));
}
__device__ __forceinline__ void ldmx2(u32* r, u32 addr) {
    asm volatile("ldmatrix.sync.aligned.m8n8.x2.shared.b16 {%0,%1}, [%2];"
                 : "=r"(r[0]), "=r"(r[1]) : "r"(addr));
}
__device__ __forceinline__ void mma_f16(float* c, const u32* a, u32 b0,
                                        u32 b1) {
    asm volatile(
        "mma.sync.aligned.m16n8k16.row.col.f32.f16.f16.f32 "
        "{%0,%1,%2,%3}, {%4,%5,%6,%7}, {%8,%9}, {%0,%1,%2,%3};"
        : "+f"(c[0]), "+f"(c[1]), "+f"(c[2]), "+f"(c[3])
        : "r"(a[0]), "r"(a[1]), "r"(a[2]), "r"(a[3]), "r"(b0), "r"(b1));
}
__device__ __forceinline__ u32 pkh2(float a, float b) {
    __half2 h = __floats2half2_rn(a, b);
    return *(u32*)&h;
}

// ---- weight prep: fp32 -> fp16 into [n][k]-row-major blob ----
__global__ void prep_kernel(const float* __restrict__ W1,
                            const float* __restrict__ W2) {
    int i = blockIdx.x * blockDim.x + threadIdx.x;
    if (i < 64 * 136) {  // W1: n 0..63, k pad to 136
        int n = i / 136, k = i % 136;
        float v = (k < 112) ? W1[n * 112 + k] : 0.0f;
        *(unsigned short*)(g_wt + SW1 + n * W1_STRIDE + k * 2) =
            __half_as_ushort(__float2half_rn(v));
    } else if (i < 64 * 136 + 32 * 72) {  // W2: n 0..31, k pad to 72
        int j = i - 64 * 136;
        int n = j / 72, k = j % 72;
        float v = (k < 64) ? W2[n * 64 + k] : 0.0f;
        *(unsigned short*)(g_wt + SW2 + n * W2_STRIDE + k * 2) =
            __half_as_ushort(__float2half_rn(v));
    }
}

// ---- main kernel: 256 threads / 8 warps.
// L1: warp = (s2 = w>>1: 2 subtiles, nh1 = w&1: N=32 = 4 ntiles)
// L2: warp = (s4 = w>>1: 2 subtiles, nh2 = w&1: N=16 = 2 ntiles) ----
__global__ __launch_bounds__(256, 2) void edge_mma(
    const float* __restrict__ src, const float* __restrict__ dst,
    const float* __restrict__ ea, const float* __restrict__ u,
    const int* __restrict__ batch32, const float* __restrict__ b1,
    const float* __restrict__ b2, float* __restrict__ out, int E, int nB) {
    extern __shared__ char sm[];
    u32 sb = smem_u32(sm);
    int tid = threadIdx.x;
    int l = tid & 31, w = tid >> 5;
    int tg = l & 3, g = l >> 2;
    int nh1 = w & 1, s2 = w >> 1;  // layer-1 roles (N=32, 2 subtiles)
    int nh2 = w & 1, s4 = w >> 1;  // layer-2 roles (N=16, 2 subtiles)

    // stage prepped weights (aliases A region)
    {
        const uint4* gw = (const uint4*)g_wt;
        uint4* sw = (uint4*)sm;
        for (int i = tid; i < WT_BYTES / 16; i += 256) sw[i] = gw[i];
    }
    __syncthreads();

    // ldmatrix B fragments into registers
    int lw = l & 15;
    int colsel = ((lw >> 3) & 1) * 16;
    u32 b1f[7][4][2];  // [chunk][ntile][reg] : N=32
    u32 b2f[4][2][2];  // N=16
#pragma unroll
    for (int nt = 0; nt < 4; nt++) {
        u32 rbase =
            sb + (u32)((nh1 * 32 + nt * 8 + (lw & 7)) * W1_STRIDE) + colsel;
#pragma unroll
        for (int c = 0; c < 7; c++) ldmx2(b1f[c][nt], rbase + SW1 + c * 32);
    }
#pragma unroll
    for (int nt = 0; nt < 2; nt++) {
        u32 rb2 =
            sb + (u32)((nh2 * 16 + nt * 8 + (lw & 7)) * W2_STRIDE) + colsel;
#pragma unroll
        for (int c = 0; c < 4; c++) ldmx2(b2f[c][nt], rb2 + SW2 + c * 32);
    }
    float bb1[4][2], bb2[2][2];
#pragma unroll
    for (int nt = 0; nt < 4; nt++) {
        bb1[nt][0] = b1[nh1 * 32 + nt * 8 + 2 * tg];
        bb1[nt][1] = b1[nh1 * 32 + nt * 8 + 2 * tg + 1];
    }
#pragma unroll
    for (int nt = 0; nt < 2; nt++) {
        bb2[nt][0] = b2[nh2 * 16 + nt * 8 + 2 * tg];
        bb2[nt][1] = b2[nh2 * 16 + nt * 8 + 2 * tg + 1];
    }

    // batch dtype detection (sorted data; int64 high word at odd tail == 0)
    int tail = batch32[E - 1];
    int tail2 = batch32[E - 2];
    bool is64 = (tail == 0) && (tail2 != 0);

    __syncthreads();  // fragments loaded before A staging overwrites W region

    u32 lrow = (u32)(((l & 7) + ((l >> 3) & 1) * 8));
    u32 ksel = ((l >> 4) & 1) * 16;

    for (int t = 0; t < TPC; t++) {
        long long eB = ((long long)blockIdx.x * TPC + t) * 128;
        if (eB >= (long long)E) break;

        // ---- stage A: 2 threads per edge, fp16, u[batch] folded ----
        {
            int el = tid >> 1, half = tid & 1;
            long long e = eB + el;
            if (e >= E) e = E - 1;
            int gidx = is64 ? batch32[2 * e] : batch32[e];
            gidx = min(max(gidx, 0), nB - 1);
            const float4* ps = (const float4*)(src + e * 32);
            const float4* pd = (const float4*)(dst + e * 32);
            const float4* pe = (const float4*)(ea + e * 32);
            const float4* pu = (const float4*)(u + (size_t)gidx * 16);
            u32 rowoff = (u32)(el * A_STRIDE + 112 * half);
#pragma unroll
            for (int j = 0; j < 14; j++) {
                float4 v;
                if (half == 0) {
                    v = (j < 8) ? ps[j] : pd[j - 8];
                } else {
                    v = (j < 2) ? pd[j + 6] : (j < 10) ? pe[j - 2] : pu[j - 10];
                }
                *(uint2*)(sm + SMA + rowoff + 8 * j) =
                    make_uint2(pkh2(v.x, v.y), pkh2(v.z, v.w));
            }
        }
        __syncthreads();

        // ---- layer 1: warp covers 2 subtiles x N=32 ----
#pragma unroll
        for (int si = 0; si < 2; si++) {
            int s = s2 * 2 + si;
            float acc[4][4] = {{0.f, 0.f, 0.f, 0.f},
                               {0.f, 0.f, 0.f, 0.f},
                               {0.f, 0.f, 0.f, 0.f},
                               {0.f, 0.f, 0.f, 0.f}};
            u32 abase = sb + (u32)((s * 16 + lrow) * A_STRIDE) + ksel;
#pragma unroll
            for (int c = 0; c < 7; c++) {
                u32 a[4];
                ldmx4(a, abase + SMA + c * 32);
#pragma unroll
                for (int nt = 0; nt < 4; nt++)
                    mma_f16(acc[nt], a, b1f[c][nt][0], b1f[c][nt][1]);
            }
            int r0 = s * 16 + g;
#pragma unroll
            for (int nt = 0; nt < 4; nt++) {
                float h0 = fmaxf(acc[nt][0] + bb1[nt][0], 0.f);
                float h1 = fmaxf(acc[nt][1] + bb1[nt][1], 0.f);
                float h2 = fmaxf(acc[nt][2] + bb1[nt][0], 0.f);
                float h3 = fmaxf(acc[nt][3] + bb1[nt][1], 0.f);
                int colb = (nh1 * 32 + nt * 8 + 2 * tg) * 2;
                *(u32*)(sm + SMH + r0 * H_STRIDE + colb) = pkh2(h0, h1);
                *(u32*)(sm + SMH + (r0 + 8) * H_STRIDE + colb) = pkh2(h2, h3);
            }
        }
        __syncthreads();

        // ---- layer 2: warp covers 2 subtiles x N=16 ----
#pragma unroll
        for (int si = 0; si < 2; si++) {
            int s = s4 * 2 + si;
            float acc[2][4] = {{0.f, 0.f, 0.f, 0.f}, {0.f, 0.f, 0.f, 0.f}};
            u32 hbase = sb + (u32)((s * 16 + lrow) * H_STRIDE) + ksel;
#pragma unroll
            for (int c = 0; c < 4; c++) {
                u32 a[4];
                ldmx4(a, hbase + SMH + c * 32);
#pragma unroll
                for (int nt = 0; nt < 2; nt++)
                    mma_f16(acc[nt], a, b2f[c][nt][0], b2f[c][nt][1]);
            }
            long long e0 = eB + s * 16 + g;
#pragma unroll
            for (int nt = 0; nt < 2; nt++) {
                int col = nh2 * 16 + nt * 8 + 2 * tg;
                if (e0 < E)
                    *(float2*)(out + e0 * 32 + col) = make_float2(
                        acc[nt][0] + bb2[nt][0], acc[nt][1] + bb2[nt][1]);
                if (e0 + 8 < E)
                    *(float2*)(out + (e0 + 8) * 32 + col) = make_float2(
                        acc[nt][2] + bb2[nt][0], acc[nt][3] + bb2[nt][1]);
            }
        }
        __syncthreads();  // h/A reads done before next tile restages
    }
}

extern "C" void kernel_launch(void* const* d_in, const int* in_sizes, int n_in,
                              void* d_out, int out_size) {
    const float* src = (const float*)d_in[0];
    const float* dst = (const float*)d_in[1];
    const float* ea = (const float*)d_in[2];
    const float* u = (const float*)d_in[3];
    const int* batch = (const int*)d_in[4];
    const float* W1 = (const float*)d_in[5];
    const float* b1 = (const float*)d_in[6];
    const float* W2 = (const float*)d_in[7];
    const float* b2 = (const float*)d_in[8];
    float* out = (float*)d_out;

    int E = in_sizes[0] / 32;
    int nB = in_sizes[3] / 16;
    if (nB > GBMAX) nB = GBMAX;

    static int init_done = 0;
    if (!init_done) {
        cudaFuncSetAttribute(edge_mma,
                             cudaFuncAttributeMaxDynamicSharedMemorySize,
                             SM_TOTAL);
        init_done = 1;
    }

    prep_kernel<<<43, 256>>>(W1, W2);
    long long tiles = ((long long)E + 127) / 128;
    int grid = (int)((tiles + TPC - 1) / TPC);
    edge_mma<<<grid, 256, SM_TOTAL>>>(src, dst, ea, u, batch, b1, b2, out, E,
                                      nB);
}

// round 8
// speedup vs baseline: 5.3981x; 1.1967x over previous
#include <cuda_runtime.h>
#include <cuda_fp16.h>

// EdgeModel via fp16 mma.sync.m16n8k16 (fp32 accum).
//   h = relu([src|dst|ea|u[batch]] @ W1^T + b1); out = h @ W2^T + b2
// R8: coalesced block staging + power-of-2 strides with 16B XOR swizzle
// (conflict-free ldmatrix/STS at minimum wavefronts). L1tex was 84.7%.

typedef unsigned int u32;

#define GBMAX 4096
#define TPC 10  // 128-edge tiles per block

// ---- smem (bytes): A 128x256 swizzled fp16 rows (src|dst|ea|u = units
// 0-13), h 128x128 swizzled fp16 rows. W blob staging aliases A. ----
#define SMA 0
#define SMH 32768
#define SM_TOTAL 49152
#define SW1 0            // W1: 64 rows x 272B (k-pad 136 fp16)
#define SW2 17408        // W2: 32 rows x 144B (k-pad 72 fp16)
#define WT_BYTES 22016
#define W1_STRIDE 272
#define W2_STRIDE 144

__device__ __align__(16) unsigned char g_wt[WT_BYTES];

// ---- helpers ----
__device__ __forceinline__ u32 smem_u32(const void* p) {
    u32 a;
    asm("{ .reg .u64 t; cvta.to.shared.u64 t, %1; cvt.u32.u64 %0, t; }"
        : "=r"(a) : "l"(p));
    return a;
}
__device__ __forceinline__ void ldmx4(u32* r, u32 addr) {
    asm volatile("ldmatrix.sync.aligned.m8n8.x4.shared.b16 {%0,%1,%2,%3}, [%4];"
                 : "=r"(r[0]), "=r"(r[1]), "=r"(r[2]), "=r"(r[3]) : "r"(addr));
}
__device__ __forceinline__ void ldmx2(u32* r, u32 addr) {
    asm volatile("ldmatrix.sync.aligned.m8n8.x2.shared.b16 {%0,%1}, [%2];"
                 : "=r"(r[0]), "=r"(r[1]) : "r"(addr));
}
__device__ __forceinline__ void mma_f16(float* c, const u32* a, u32 b0,
                                        u32 b1) {
    asm volatile(
        "mma.sync.aligned.m16n8k16.row.col.f32.f16.f16.f32 "
        "{%0,%1,%2,%3}, {%4,%5,%6,%7}, {%8,%9}, {%0,%1,%2,%3};"
        : "+f"(c[0]), "+f"(c[1]), "+f"(c[2]), "+f"(c[3])
        : "r"(a[0]), "r"(a[1]), "r"(a[2]), "r"(a[3]), "r"(b0), "r"(b1));
}
__device__ __forceinline__ u32 pkh2(float a, float b) {
    __half2 h = __floats2half2_rn(a, b);
    return *(u32*)&h;
}

// ---- weight prep: fp32 -> fp16 into [n][k]-row-major blob ----
__global__ void prep_kernel(const float* __restrict__ W1,
                            const float* __restrict__ W2) {
    int i = blockIdx.x * blockDim.x + threadIdx.x;
    if (i < 64 * 136) {
        int n = i / 136, k = i % 136;
        float v = (k < 112) ? W1[n * 112 + k] : 0.0f;
        *(unsigned short*)(g_wt + SW1 + n * W1_STRIDE + k * 2) =
            __half_as_ushort(__float2half_rn(v));
    } else if (i < 64 * 136 + 32 * 72) {
        int j = i - 64 * 136;
        int n = j / 72, k = j % 72;
        float v = (k < 64) ? W2[n * 64 + k] : 0.0f;
        *(unsigned short*)(g_wt + SW2 + n * W2_STRIDE + k * 2) =
            __half_as_ushort(__float2half_rn(v));
    }
}

// ---- main kernel: 256 threads / 8 warps.
// L1: warp = (s2 = w>>1: 2 subtiles, nh1 = w&1: N=32 = 4 ntiles)
// L2: warp = (s4 = w>>1: 2 subtiles, nh2 = w&1: N=16 = 2 ntiles) ----
__global__ __launch_bounds__(256, 2) void edge_mma(
    const float* __restrict__ src, const float* __restrict__ dst,
    const float* __restrict__ ea, const float* __restrict__ u,
    const int* __restrict__ batch32, const float* __restrict__ b1,
    const float* __restrict__ b2, float* __restrict__ out, int E, int nB) {
    extern __shared__ char sm[];
    u32 sb = smem_u32(sm);
    int tid = threadIdx.x;
    int l = tid & 31, w = tid >> 5;
    int tg = l & 3, g = l >> 2;
    int nh1 = w & 1, s2 = w >> 1;
    int nh2 = w & 1, s4 = w >> 1;

    // stage prepped weights (aliases A region)
    {
        const uint4* gw = (const uint4*)g_wt;
        uint4* sw = (uint4*)sm;
        for (int i = tid; i < WT_BYTES / 16; i += 256) sw[i] = gw[i];
    }
    __syncthreads();

    // ldmatrix B fragments into registers
    int lw = l & 15;
    int colsel = ((lw >> 3) & 1) * 16;
    u32 b1f[7][4][2];  // N=32
    u32 b2f[4][2][2];  // N=16
#pragma unroll
    for (int nt = 0; nt < 4; nt++) {
        u32 rbase =
            sb + (u32)((nh1 * 32 + nt * 8 + (lw & 7)) * W1_STRIDE) + colsel;
#pragma unroll
        for (int c = 0; c < 7; c++) ldmx2(b1f[c][nt], rbase + SW1 + c * 32);
    }
#pragma unroll
    for (int nt = 0; nt < 2; nt++) {
        u32 rb2 =
            sb + (u32)((nh2 * 16 + nt * 8 + (lw & 7)) * W2_STRIDE) + colsel;
#pragma unroll
        for (int c = 0; c < 4; c++) ldmx2(b2f[c][nt], rb2 + SW2 + c * 32);
    }
    float bb1[4][2], bb2[2][2];
#pragma unroll
    for (int nt = 0; nt < 4; nt++) {
        bb1[nt][0] = b1[nh1 * 32 + nt * 8 + 2 * tg];
        bb1[nt][1] = b1[nh1 * 32 + nt * 8 + 2 * tg + 1];
    }
#pragma unroll
    for (int nt = 0; nt < 2; nt++) {
        bb2[nt][0] = b2[nh2 * 16 + nt * 8 + 2 * tg];
        bb2[nt][1] = b2[nh2 * 16 + nt * 8 + 2 * tg + 1];
    }

    // batch dtype detection (sorted data; int64 high word at odd tail == 0)
    int tail = batch32[E - 1];
    int tail2 = batch32[E - 2];
    bool is64 = (tail == 0) && (tail2 != 0);

    __syncthreads();  // fragments loaded before A staging overwrites W region

    int lk = l & 7;
    int khi = (l >> 4) & 1;
    u32 lrow = (u32)((l & 7) + ((l >> 3) & 1) * 8);

    for (int t = 0; t < TPC; t++) {
        long long eB = ((long long)blockIdx.x * TPC + t) * 128;
        if (eB >= (long long)E) break;

        // ---- stage A (coalesced): 3 contiguous 16KB blocks -> fp16 ----
        // phys unit = logical_unit ^ (edge & 7); units: src 0-3, dst 4-7,
        // ea 8-11, u 12-13.
#pragma unroll
        for (int r = 0; r < 3; r++) {
            const float* bp = (r == 0) ? src : (r == 1) ? dst : ea;
#pragma unroll
            for (int it = 0; it < 2; it++) {
                int mI = it * 256 + tid;  // 512 units per region
                int edge = mI >> 2, uu = mI & 3;
                long long ee = eB + edge;
                if (ee >= E) ee = E - 1;
                const float4* p = (const float4*)(bp + ee * 32 + uu * 8);
                float4 v0 = p[0], v1 = p[1];
                uint4 wv = make_uint4(pkh2(v0.x, v0.y), pkh2(v0.z, v0.w),
                                      pkh2(v1.x, v1.y), pkh2(v1.z, v1.w));
                int unit = r * 4 + uu;
                *(uint4*)(sm + SMA + edge * 256 +
                          ((unit ^ (edge & 7)) << 4)) = wv;
            }
        }
        if (tid < 128) {  // u[batch] gather -> units 12,13
            int edge = tid;
            long long e = eB + edge;
            if (e >= E) e = E - 1;
            int gidx = is64 ? batch32[2 * e] : batch32[e];
            gidx = min(max(gidx, 0), nB - 1);
            const float4* pu = (const float4*)(u + (size_t)gidx * 16);
            float4 a0 = pu[0], a1 = pu[1], a2 = pu[2], a3 = pu[3];
            uint4 w0 = make_uint4(pkh2(a0.x, a0.y), pkh2(a0.z, a0.w),
                                  pkh2(a1.x, a1.y), pkh2(a1.z, a1.w));
            uint4 w1 = make_uint4(pkh2(a2.x, a2.y), pkh2(a2.z, a2.w),
                                  pkh2(a3.x, a3.y), pkh2(a3.z, a3.w));
            int key = edge & 7;
            *(uint4*)(sm + SMA + edge * 256 + ((12 ^ key) << 4)) = w0;
            *(uint4*)(sm + SMA + edge * 256 + ((13 ^ key) << 4)) = w1;
        }
        __syncthreads();

        // ---- layer 1: warp covers 2 subtiles x N=32 ----
#pragma unroll
        for (int si = 0; si < 2; si++) {
            int s = s2 * 2 + si;
            float acc[4][4] = {{0.f, 0.f, 0.f, 0.f},
                               {0.f, 0.f, 0.f, 0.f},
                               {0.f, 0.f, 0.f, 0.f},
                               {0.f, 0.f, 0.f, 0.f}};
            u32 rowb = sb + SMA + (u32)((s * 16 + lrow) * 256);
#pragma unroll
            for (int c = 0; c < 7; c++) {
                u32 a[4];
                ldmx4(a, rowb + (u32)(((2 * c + khi) ^ lk) << 4));
#pragma unroll
                for (int nt = 0; nt < 4; nt++)
                    mma_f16(acc[nt], a, b1f[c][nt][0], b1f[c][nt][1]);
            }
            int r0 = s * 16 + g;
#pragma unroll
            for (int nt = 0; nt < 4; nt++) {
                float h0 = fmaxf(acc[nt][0] + bb1[nt][0], 0.f);
                float h1 = fmaxf(acc[nt][1] + bb1[nt][1], 0.f);
                float h2 = fmaxf(acc[nt][2] + bb1[nt][0], 0.f);
                float h3 = fmaxf(acc[nt][3] + bb1[nt][1], 0.f);
                int unit = 4 * nh1 + nt;  // 16B unit within 128B h row
                u32 hoff = (u32)(r0 * 128 + ((unit ^ g) << 4) + 4 * tg);
                *(u32*)(sm + SMH + hoff) = pkh2(h0, h1);
                *(u32*)(sm + SMH + hoff + 8 * 128) = pkh2(h2, h3);
            }
        }
        __syncthreads();

        // ---- layer 2: warp covers 2 subtiles x N=16 ----
#pragma unroll
        for (int si = 0; si < 2; si++) {
            int s = s4 * 2 + si;
            float acc[2][4] = {{0.f, 0.f, 0.f, 0.f}, {0.f, 0.f, 0.f, 0.f}};
            u32 rowb = sb + SMH + (u32)((s * 16 + lrow) * 128);
#pragma unroll
            for (int c = 0; c < 4; c++) {
                u32 a[4];
                ldmx4(a, rowb + (u32)(((2 * c + khi) ^ lk) << 4));
#pragma unroll
                for (int nt = 0; nt < 2; nt++)
                    mma_f16(acc[nt], a, b2f[c][nt][0], b2f[c][nt][1]);
            }
            long long e0 = eB + s * 16 + g;
#pragma unroll
            for (int nt = 0; nt < 2; nt++) {
                int col = nh2 * 16 + nt * 8 + 2 * tg;
                if (e0 < E)
                    *(float2*)(out + e0 * 32 + col) = make_float2(
                        acc[nt][0] + bb2[nt][0], acc[nt][1] + bb2[nt][1]);
                if (e0 + 8 < E)
                    *(float2*)(out + (e0 + 8) * 32 + col) = make_float2(
                        acc[nt][2] + bb2[nt][0], acc[nt][3] + bb2[nt][1]);
            }
        }
        // no end-of-loop sync needed: next staging writes A/u regions only,
        // whose last readers (layer-1 LDSM) are ordered by the h-store sync.
    }
}

extern "C" void kernel_launch(void* const* d_in, const int* in_sizes, int n_in,
                              void* d_out, int out_size) {
    const float* src = (const float*)d_in[0];
    const float* dst = (const float*)d_in[1];
    const float* ea = (const float*)d_in[2];
    const float* u = (const float*)d_in[3];
    const int* batch = (const int*)d_in[4];
    const float* W1 = (const float*)d_in[5];
    const float* b1 = (const float*)d_in[6];
    const float* W2 = (const float*)d_in[7];
    const float* b2 = (const float*)d_in[8];
    float* out = (float*)d_out;

    int E = in_sizes[0] / 32;
    int nB = in_sizes[3] / 16;
    if (nB > GBMAX) nB = GBMAX;

    static int init_done = 0;
    if (!init_done) {
        cudaFuncSetAttribute(edge_mma,
                             cudaFuncAttributeMaxDynamicSharedMemorySize,
                             SM_TOTAL);
        init_done = 1;
    }

    prep_kernel<<<43, 256>>>(W1, W2);
    long long tiles = ((long long)E + 127) / 128;
    int grid = (int)((tiles + TPC - 1) / TPC);
    edge_mma<<<grid, 256, SM_TOTAL>>>(src, dst, ea, u, batch, b1, b2, out, E,
                                      nB);
}

// round 9
// speedup vs baseline: 6.8778x; 1.2741x over previous
#include <cuda_runtime.h>
#include <cuda_fp16.h>

// EdgeModel via fp16 mma.sync.m16n8k16 (fp32 accum).
//   h = relu([src|dst|ea|u[batch]] @ W1^T + b1); out = h @ W2^T + b2
// R9: cp.async double-buffered staging. R8 was phase-serialized latency
// bound (DRAM 47%, L1 56%, issue 17%, nothing saturated): LDG->STS->sync->MMA
// in strict sequence. Now tile t+1's global fetch overlaps tile t's MMAs.

typedef unsigned int u32;

#define GBMAX 4096
#define TPC 10  // 128-edge tiles per block

// ---- smem (bytes) ----
#define STAGE 0          // fp32 staging: 3 regions x 16KB
#define SMA 49152        // A: 128 rows x 256B fp16, XOR-swizzled 16B units
#define SMH 81920        // h: 128 rows x 128B fp16, XOR-swizzled
#define SM_TOTAL 98304
#define SW1 49152        // W blob staging aliases A region
#define SW2 (49152 + 17408)
#define WT_BYTES 22016
#define W1_STRIDE 272
#define W2_STRIDE 144

__device__ __align__(16) unsigned char g_wt[WT_BYTES];

// ---- helpers ----
__device__ __forceinline__ u32 smem_u32(const void* p) {
    u32 a;
    asm("{ .reg .u64 t; cvta.to.shared.u64 t, %1; cvt.u32.u64 %0, t; }"
        : "=r"(a) : "l"(p));
    return a;
}
__device__ __forceinline__ void ldmx4(u32* r, u32 addr) {
    asm volatile("ldmatrix.sync.aligned.m8n8.x4.shared.b16 {%0,%1,%2,%3}, [%4];"
                 : "=r"(r[0]), "=r"(r[1]), "=r"(r[2]), "=r"(r[3]) : "r"(addr));
}
__device__ __forceinline__ void ldmx2(u32* r, u32 addr) {
    asm volatile("ldmatrix.sync.aligned.m8n8.x2.shared.b16 {%0,%1}, [%2];"
                 : "=r"(r[0]), "=r"(r[1]) : "r"(addr));
}
__device__ __forceinline__ void mma_f16(float* c, const u32* a, u32 b0,
                                        u32 b1) {
    asm volatile(
        "mma.sync.aligned.m16n8k16.row.col.f32.f16.f16.f32 "
        "{%0,%1,%2,%3}, {%4,%5,%6,%7}, {%8,%9}, {%0,%1,%2,%3};"
        : "+f"(c[0]), "+f"(c[1]), "+f"(c[2]), "+f"(c[3])
        : "r"(a[0]), "r"(a[1]), "r"(a[2]), "r"(a[3]), "r"(b0), "r"(b1));
}
__device__ __forceinline__ u32 pkh2(float a, float b) {
    __half2 h = __floats2half2_rn(a, b);
    return *(u32*)&h;
}
__device__ __forceinline__ void cpasync16(u32 dst, const void* src) {
    asm volatile("cp.async.cg.shared.global [%0], [%1], 16;" ::
                 "r"(dst), "l"(src));
}
#define CP_COMMIT() asm volatile("cp.async.commit_group;" ::: "memory")
#define CP_WAIT0() asm volatile("cp.async.wait_group 0;" ::: "memory")

// issue one tile's staging (3 x 16KB fp32) via cp.async; 12 chunks/thread
__device__ __forceinline__ void issue_stage(u32 sb, const float* __restrict__ src,
                                            const float* __restrict__ dst,
                                            const float* __restrict__ ea,
                                            long long eB, int E, int tid) {
#pragma unroll
    for (int r = 0; r < 3; r++) {
        const float* bp = (r == 0) ? src : (r == 1) ? dst : ea;
#pragma unroll
        for (int it = 0; it < 4; it++) {
            int chunk = it * 256 + tid;  // 1024 x 16B per region
            int edge = chunk >> 3, q = chunk & 7;
            long long ee = eB + edge;
            if (ee >= E) ee = E - 1;
            cpasync16(sb + STAGE + r * 16384 + chunk * 16,
                      bp + ee * 32 + q * 4);
        }
    }
    CP_COMMIT();
}

// ---- weight prep: fp32 -> fp16 into [n][k]-row-major blob ----
__global__ void prep_kernel(const float* __restrict__ W1,
                            const float* __restrict__ W2) {
    int i = blockIdx.x * blockDim.x + threadIdx.x;
    if (i < 64 * 136) {
        int n = i / 136, k = i % 136;
        float v = (k < 112) ? W1[n * 112 + k] : 0.0f;
        *(unsigned short*)(g_wt + n * W1_STRIDE + k * 2) =
            __half_as_ushort(__float2half_rn(v));
    } else if (i < 64 * 136 + 32 * 72) {
        int j = i - 64 * 136;
        int n = j / 72, k = j % 72;
        float v = (k < 64) ? W2[n * 64 + k] : 0.0f;
        *(unsigned short*)(g_wt + 17408 + n * W2_STRIDE + k * 2) =
            __half_as_ushort(__float2half_rn(v));
    }
}

// ---- main kernel: 256 threads / 8 warps.
// L1: warp = (s2 = w>>1: 2 subtiles, nh1 = w&1: N=32 = 4 ntiles)
// L2: warp = (s4 = w>>1: 2 subtiles, nh2 = w&1: N=16 = 2 ntiles) ----
__global__ __launch_bounds__(256, 2) void edge_mma(
    const float* __restrict__ src, const float* __restrict__ dst,
    const float* __restrict__ ea, const float* __restrict__ u,
    const int* __restrict__ batch32, const float* __restrict__ b1,
    const float* __restrict__ b2, float* __restrict__ out, int E, int nB) {
    extern __shared__ char sm[];
    u32 sb = smem_u32(sm);
    int tid = threadIdx.x;
    int l = tid & 31, w = tid >> 5;
    int tg = l & 3, g = l >> 2;
    int nh1 = w & 1, s2 = w >> 1;
    int nh2 = w & 1, s4 = w >> 1;

    // prologue: kick off tile 0's async staging immediately
    long long eB0 = (long long)blockIdx.x * TPC * 128;
    issue_stage(sb, src, dst, ea, eB0, E, tid);

    // stage prepped weights (aliases A region; STAGE untouched)
    {
        const uint4* gw = (const uint4*)g_wt;
        uint4* sw = (uint4*)(sm + SW1);
        for (int i = tid; i < WT_BYTES / 16; i += 256) sw[i] = gw[i];
    }
    __syncthreads();

    // ldmatrix B fragments into registers
    int lw = l & 15;
    int colsel = ((lw >> 3) & 1) * 16;
    u32 b1f[7][4][2];  // N=32
    u32 b2f[4][2][2];  // N=16
#pragma unroll
    for (int nt = 0; nt < 4; nt++) {
        u32 rbase =
            sb + SW1 + (u32)((nh1 * 32 + nt * 8 + (lw & 7)) * W1_STRIDE) + colsel;
#pragma unroll
        for (int c = 0; c < 7; c++) ldmx2(b1f[c][nt], rbase + c * 32);
    }
#pragma unroll
    for (int nt = 0; nt < 2; nt++) {
        u32 rb2 =
            sb + SW2 + (u32)((nh2 * 16 + nt * 8 + (lw & 7)) * W2_STRIDE) + colsel;
#pragma unroll
        for (int c = 0; c < 4; c++) ldmx2(b2f[c][nt], rb2 + c * 32);
    }
    float bb1[4][2], bb2[2][2];
#pragma unroll
    for (int nt = 0; nt < 4; nt++) {
        bb1[nt][0] = b1[nh1 * 32 + nt * 8 + 2 * tg];
        bb1[nt][1] = b1[nh1 * 32 + nt * 8 + 2 * tg + 1];
    }
#pragma unroll
    for (int nt = 0; nt < 2; nt++) {
        bb2[nt][0] = b2[nh2 * 16 + nt * 8 + 2 * tg];
        bb2[nt][1] = b2[nh2 * 16 + nt * 8 + 2 * tg + 1];
    }

    // batch dtype detection (sorted data; int64 high word at odd tail == 0)
    int tail = batch32[E - 1];
    int tail2 = batch32[E - 2];
    bool is64 = (tail == 0) && (tail2 != 0);

    __syncthreads();  // fragments loaded before convert pass writes A region

    int lk = l & 7;
    int khi = (l >> 4) & 1;
    u32 lrow = (u32)((l & 7) + ((l >> 3) & 1) * 8);

    for (int t = 0; t < TPC; t++) {
        long long eB = ((long long)blockIdx.x * TPC + t) * 128;
        if (eB >= (long long)E) break;

        CP_WAIT0();
        __syncthreads();  // staged fp32 visible to all; prev tile fully done

        // ---- convert pass: fp32 stage -> fp16 A (swizzled units 0-11) ----
#pragma unroll
        for (int r = 0; r < 3; r++) {
#pragma unroll
            for (int it = 0; it < 2; it++) {
                int uidx = it * 256 + tid;  // 512 units per region
                int edge = uidx >> 2, uu = uidx & 3;
                const float4* p =
                    (const float4*)(sm + STAGE + r * 16384 + edge * 128 +
                                    uu * 32);
                float4 v0 = p[0], v1 = p[1];
                uint4 wv = make_uint4(pkh2(v0.x, v0.y), pkh2(v0.z, v0.w),
                                      pkh2(v1.x, v1.y), pkh2(v1.z, v1.w));
                int unit = r * 4 + uu;
                *(uint4*)(sm + SMA + edge * 256 +
                          ((unit ^ (edge & 7)) << 4)) = wv;
            }
        }
        if (tid < 128) {  // u[batch] gather -> units 12,13
            int edge = tid;
            long long e = eB + edge;
            if (e >= E) e = E - 1;
            int gidx = is64 ? batch32[2 * e] : batch32[e];
            gidx = min(max(gidx, 0), nB - 1);
            const float4* pu = (const float4*)(u + (size_t)gidx * 16);
            float4 a0 = pu[0], a1 = pu[1], a2 = pu[2], a3 = pu[3];
            uint4 w0 = make_uint4(pkh2(a0.x, a0.y), pkh2(a0.z, a0.w),
                                  pkh2(a1.x, a1.y), pkh2(a1.z, a1.w));
            uint4 w1 = make_uint4(pkh2(a2.x, a2.y), pkh2(a2.z, a2.w),
                                  pkh2(a3.x, a3.y), pkh2(a3.z, a3.w));
            int key = edge & 7;
            *(uint4*)(sm + SMA + edge * 256 + ((12 ^ key) << 4)) = w0;
            *(uint4*)(sm + SMA + edge * 256 + ((13 ^ key) << 4)) = w1;
        }
        __syncthreads();  // A ready; STAGE reads done -> safe to refill

        // ---- prefetch next tile's staging (overlaps both MMA phases) ----
        long long eBn = eB + 128;
        if (t + 1 < TPC && eBn < (long long)E)
            issue_stage(sb, src, dst, ea, eBn, E, tid);

        // ---- layer 1: warp covers 2 subtiles x N=32 ----
#pragma unroll
        for (int si = 0; si < 2; si++) {
            int s = s2 * 2 + si;
            float acc[4][4] = {{0.f, 0.f, 0.f, 0.f},
                               {0.f, 0.f, 0.f, 0.f},
                               {0.f, 0.f, 0.f, 0.f},
                               {0.f, 0.f, 0.f, 0.f}};
            u32 rowb = sb + SMA + (u32)((s * 16 + lrow) * 256);
#pragma unroll
            for (int c = 0; c < 7; c++) {
                u32 a[4];
                ldmx4(a, rowb + (u32)(((2 * c + khi) ^ lk) << 4));
#pragma unroll
                for (int nt = 0; nt < 4; nt++)
                    mma_f16(acc[nt], a, b1f[c][nt][0], b1f[c][nt][1]);
            }
            int r0 = s * 16 + g;
#pragma unroll
            for (int nt = 0; nt < 4; nt++) {
                float h0 = fmaxf(acc[nt][0] + bb1[nt][0], 0.f);
                float h1 = fmaxf(acc[nt][1] + bb1[nt][1], 0.f);
                float h2 = fmaxf(acc[nt][2] + bb1[nt][0], 0.f);
                float h3 = fmaxf(acc[nt][3] + bb1[nt][1], 0.f);
                int unit = 4 * nh1 + nt;
                u32 hoff = (u32)(r0 * 128 + ((unit ^ g) << 4) + 4 * tg);
                *(u32*)(sm + SMH + hoff) = pkh2(h0, h1);
                *(u32*)(sm + SMH + hoff + 8 * 128) = pkh2(h2, h3);
            }
        }
        __syncthreads();

        // ---- layer 2: warp covers 2 subtiles x N=16 ----
#pragma unroll
        for (int si = 0; si < 2; si++) {
            int s = s4 * 2 + si;
            float acc[2][4] = {{0.f, 0.f, 0.f, 0.f}, {0.f, 0.f, 0.f, 0.f}};
            u32 rowb = sb + SMH + (u32)((s * 16 + lrow) * 128);
#pragma unroll
            for (int c = 0; c < 4; c++) {
                u32 a[4];
                ldmx4(a, rowb + (u32)(((2 * c + khi) ^ lk) << 4));
#pragma unroll
                for (int nt = 0; nt < 2; nt++)
                    mma_f16(acc[nt], a, b2f[c][nt][0], b2f[c][nt][1]);
            }
            long long e0 = eB + s * 16 + g;
#pragma unroll
            for (int nt = 0; nt < 2; nt++) {
                int col = nh2 * 16 + nt * 8 + 2 * tg;
                if (e0 < E)
                    *(float2*)(out + e0 * 32 + col) = make_float2(
                        acc[nt][0] + bb2[nt][0], acc[nt][1] + bb2[nt][1]);
                if (e0 + 8 < E)
                    *(float2*)(out + (e0 + 8) * 32 + col) = make_float2(
                        acc[nt][2] + bb2[nt][0], acc[nt][3] + bb2[nt][1]);
            }
        }
        // loop-top sync orders h reads (L2) before next tile's h writes
    }
}

extern "C" void kernel_launch(void* const* d_in, const int* in_sizes, int n_in,
                              void* d_out, int out_size) {
    const float* src = (const float*)d_in[0];
    const float* dst = (const float*)d_in[1];
    const float* ea = (const float*)d_in[2];
    const float* u = (const float*)d_in[3];
    const int* batch = (const int*)d_in[4];
    const float* W1 = (const float*)d_in[5];
    const float* b1 = (const float*)d_in[6];
    const float* W2 = (const float*)d_in[7];
    const float* b2 = (const float*)d_in[8];
    float* out = (float*)d_out;

    int E = in_sizes[0] / 32;
    int nB = in_sizes[3] / 16;
    if (nB > GBMAX) nB = GBMAX;

    static int init_done = 0;
    if (!init_done) {
        cudaFuncSetAttribute(edge_mma,
                             cudaFuncAttributeMaxDynamicSharedMemorySize,
                             SM_TOTAL);
        init_done = 1;
    }

    prep_kernel<<<43, 256>>>(W1, W2);
    long long tiles = ((long long)E + 127) / 128;
    int grid = (int)((tiles + TPC - 1) / TPC);
    edge_mma<<<grid, 256, SM_TOTAL>>>(src, dst, ea, u, batch, b1, b2, out, E,
                                      nB);
}